// round 13
// baseline (speedup 1.0000x reference)
#include <cuda_runtime.h>
#include <cuda_fp16.h>
#include <math.h>
#include <stdint.h>

#define BB   8
#define SS   512
#define HH   768
#define NHH  12
#define DHH  64
#define FFF  3072
#define MM   (BB * SS)
#define LN_EPS 1e-3f

// ---------------------------------------------------------------------------
// Scratch
// ---------------------------------------------------------------------------
__device__ __align__(16) __half g_xh  [MM * HH];
__device__ __align__(16) __half g_qkvh[MM * 3 * HH];
__device__ __align__(16) __half g_ctxh[MM * HH];
__device__ __align__(16) float g_t1 [MM * HH];
__device__ __align__(16) float g_h1 [MM * HH];
__device__ __align__(16) __half g_h1h[MM * HH];
__device__ __align__(16) __half g_ffh[MM * FFF];
__device__ __align__(16) float g_t2 [MM * HH];
__device__ __align__(16) __half g_wqkv[3 * HH * HH];
__device__ __align__(16) float g_bqkv[3 * HH];
__device__ __align__(16) __half g_wo [HH * HH];
__device__ __align__(16) __half g_w1 [FFF * HH];
__device__ __align__(16) __half g_w2 [HH * FFF];

// ---------------------------------------------------------------------------
// PTX wrappers
// ---------------------------------------------------------------------------
__device__ __forceinline__ uint32_t smem_u32(const void* p) {
    uint32_t a;
    asm("{ .reg .u64 t; cvta.to.shared.u64 t, %1; cvt.u32.u64 %0, t; }"
        : "=r"(a) : "l"(p));
    return a;
}
#define LDM4(R, ADDR) \
    asm volatile("ldmatrix.sync.aligned.m8n8.x4.shared.b16 {%0,%1,%2,%3}, [%4];" \
        : "=r"((R)[0]), "=r"((R)[1]), "=r"((R)[2]), "=r"((R)[3]) : "r"(ADDR))
#define LDM4T(R, ADDR) \
    asm volatile("ldmatrix.sync.aligned.m8n8.x4.trans.shared.b16 {%0,%1,%2,%3}, [%4];" \
        : "=r"((R)[0]), "=r"((R)[1]), "=r"((R)[2]), "=r"((R)[3]) : "r"(ADDR))
#define MMAF16(D, A, B0, B1) \
    asm volatile("mma.sync.aligned.m16n8k16.row.col.f32.f16.f16.f32 " \
        "{%0,%1,%2,%3}, {%4,%5,%6,%7}, {%8,%9}, {%0,%1,%2,%3};" \
        : "+f"((D)[0]), "+f"((D)[1]), "+f"((D)[2]), "+f"((D)[3]) \
        : "r"((A)[0]), "r"((A)[1]), "r"((A)[2]), "r"((A)[3]), "r"(B0), "r"(B1))
#define CP16(SADDR, GPTR) \
    asm volatile("cp.async.cg.shared.global [%0], [%1], 16;" \
        :: "r"(SADDR), "l"(GPTR))
#define CP_COMMIT() asm volatile("cp.async.commit_group;" ::: "memory")
#define CP_WAIT(N)  asm volatile("cp.async.wait_group %0;" :: "n"(N) : "memory")

__device__ __forceinline__ float gelu_f(float x) {
    return 0.5f * x * (1.0f + erff(x * 0.70710678118654752f));
}

// ---------------------------------------------------------------------------
// Fused prep kernel (unchanged)
// ---------------------------------------------------------------------------
#define PREP_BLOCKS 9985

__global__ void __launch_bounds__(256) prep_kernel(
    const float* __restrict__ Wq, const float* __restrict__ Wk,
    const float* __restrict__ Wv, const float* __restrict__ Wo,
    const float* __restrict__ W1, const float* __restrict__ W2,
    const float* __restrict__ x,
    const float* __restrict__ bq, const float* __restrict__ bk,
    const float* __restrict__ bv,
    __half* __restrict__ wqkv, __half* __restrict__ wo,
    __half* __restrict__ w1, __half* __restrict__ w2,
    __half* __restrict__ xh, float* __restrict__ bqkv)
{
    __shared__ float tile[32][33];
    const int id = blockIdx.x;
    const int t  = threadIdx.x;
    const int tx = t & 31, ty = t >> 5;

    const float* in = nullptr;
    __half* out = nullptr;
    int K = 0, N = 0, bx = 0, by = 0;

    if (id < 2304) {
        const int z = id / 576, within = id % 576;
        in  = (z == 0) ? Wq : (z == 1) ? Wk : (z == 2) ? Wv : Wo;
        out = (z < 3) ? (wqkv + z * HH * HH) : wo;
        K = HH; N = HH; bx = within % 24; by = within / 24;
    } else if (id < 4608) {
        const int within = id - 2304;
        in = W1; out = w1; K = HH; N = FFF;
        bx = within % 96; by = within / 96;
    } else if (id < 6912) {
        const int within = id - 4608;
        in = W2; out = w2; K = FFF; N = HH;
        bx = within % 24; by = within / 24;
    } else if (id < 9984) {
        const int i = (id - 6912) * 256 + t;
        const float4 v = *(const float4*)(x + (size_t)i * 4);
        __half2 h0 = __floats2half2_rn(v.x, v.y);
        __half2 h1 = __floats2half2_rn(v.z, v.w);
        uint2 u; u.x = *(uint32_t*)&h0; u.y = *(uint32_t*)&h1;
        *(uint2*)(xh + (size_t)i * 4) = u;
        return;
    } else {
        for (int i = t; i < HH; i += 256) {
            bqkv[i] = bq[i]; bqkv[HH + i] = bk[i]; bqkv[2 * HH + i] = bv[i];
        }
        return;
    }

    const int n0 = bx * 32, k0 = by * 32;
#pragma unroll
    for (int j = 0; j < 32; j += 8)
        tile[ty + j][tx] = in[(size_t)(k0 + ty + j) * N + n0 + tx];
    __syncthreads();
#pragma unroll
    for (int j = 0; j < 32; j += 8)
        out[(size_t)(n0 + ty + j) * K + k0 + tx] = __float2half_rn(tile[tx][ty + j]);
}

// ---------------------------------------------------------------------------
// GEMM: fp16, KC=64, 2-stage, 1 sync/chunk. BN=64, warp grid 4x2.
//   MT=2 -> BM=128 (stage 55.3KB, 4 CTA/SM); MT=1 -> BM=64 (36.9KB, 6 CTA/SM)
// ---------------------------------------------------------------------------
#define KC 64
#define ROWB 144
#define NSTAGE 2

template <int EPI, int MT>
__global__ void __launch_bounds__(256) tc_gemm(
    const __half* __restrict__ Ahi,
    const __half* __restrict__ Whi,
    const float* __restrict__ bias, const float* __restrict__ resid,
    float* __restrict__ C, __half* __restrict__ Chi,
    int K, int Ntot)
{
    constexpr int BM = 64 * MT;
    constexpr int AMATB = BM * ROWB;
    constexpr int BMATB = 64 * ROWB;
    constexpr int STAGEB = AMATB + BMATB;
    constexpr int ACH = BM * 8;
    constexpr int BCH = 64 * 8;
    constexpr int NCHK = (ACH + BCH) / 256;

    extern __shared__ char sm[];
    const uint32_t sb = smem_u32(sm);

    const int t    = threadIdx.x;
    const int wid  = t >> 5, lane = t & 31;
    const int wm   = wid >> 1;          // 0..3
    const int wn   = wid & 1;           // 0..1
    const int bn   = blockIdx.x, bm = blockIdx.y;
    const int rbase = bm * BM, cbase = bn * 64;
    const int nch  = K / KC;

    auto issue = [&](int ci) {
        const int s = ci & 1;
        const uint32_t st = sb + s * STAGEB;
        const int kt = ci * KC;
#pragma unroll
        for (int j = 0; j < NCHK; j++) {
            int id = t + j * 256;
            if (id < ACH) {
                const int r = id >> 3, c = id & 7;
                CP16(st + r * ROWB + c * 16,
                     Ahi + (size_t)(rbase + r) * K + kt + c * 8);
            } else {
                id -= ACH;
                const int r = id >> 3, c = id & 7;
                CP16(st + AMATB + r * ROWB + c * 16,
                     Whi + (size_t)(cbase + r) * K + kt + c * 8);
            }
        }
    };

    float acc[MT][4][4];
#pragma unroll
    for (int i = 0; i < MT; i++)
#pragma unroll
        for (int j = 0; j < 4; j++)
#pragma unroll
            for (int q = 0; q < 4; q++) acc[i][j][q] = 0.f;

    const uint32_t a_off = (uint32_t)((wm * (MT * 16) + (lane & 15)) * ROWB
                                      + ((lane >> 4) << 4));
    const uint32_t b_off = (uint32_t)((wn * 32 + ((lane & 7) | ((lane & 16) >> 1))) * ROWB
                                      + (((lane >> 3) & 1) << 4));

    issue(0); CP_COMMIT();

    for (int ci = 0; ci < nch; ci++) {
        CP_WAIT(0);
        __syncthreads();
        if (ci + 1 < nch) { issue(ci + 1); CP_COMMIT(); }

        const uint32_t sA  = sb + (ci & 1) * STAGEB;
        const uint32_t sBh = sA + AMATB;
#pragma unroll
        for (int ks = 0; ks < 4; ks++) {
            const uint32_t ko = ks * 32;
            uint32_t AH[MT][4], BH[2][4];
#pragma unroll
            for (int mt = 0; mt < MT; mt++)
                LDM4(AH[mt], sA + a_off + mt * (16 * ROWB) + ko);
#pragma unroll
            for (int n2 = 0; n2 < 2; n2++)
                LDM4(BH[n2], sBh + b_off + n2 * (16 * ROWB) + ko);
#pragma unroll
            for (int mt = 0; mt < MT; mt++) {
#pragma unroll
                for (int nt = 0; nt < 4; nt++) {
                    const uint32_t b0 = BH[nt >> 1][(nt & 1) * 2];
                    const uint32_t b1 = BH[nt >> 1][(nt & 1) * 2 + 1];
                    MMAF16(acc[mt][nt], AH[mt], b0, b1);
                }
            }
        }
    }

    const int mrow0 = rbase + wm * (MT * 16) + (lane >> 2);
    const int ncol0 = cbase + wn * 32 + (lane & 3) * 2;
#pragma unroll
    for (int mt = 0; mt < MT; mt++) {
#pragma unroll
        for (int half = 0; half < 2; half++) {
            const int m = mrow0 + mt * 16 + half * 8;
            const size_t rowoff = (size_t)m * Ntot;
#pragma unroll
            for (int nt = 0; nt < 4; nt++) {
                const int n = ncol0 + nt * 8;
                float v0 = acc[mt][nt][half * 2 + 0];
                float v1 = acc[mt][nt][half * 2 + 1];
                const float2 bv = *(const float2*)(bias + n);
                v0 += bv.x; v1 += bv.y;
                if (EPI == 2) {
                    const float2 rv = *(const float2*)(resid + rowoff + n);
                    v0 += rv.x; v1 += rv.y;
                    *(float2*)(C + rowoff + n) = make_float2(v0, v1);
                } else {
                    if (EPI == 1) { v0 = gelu_f(v0); v1 = gelu_f(v1); }
                    __half2 hh = __floats2half2_rn(v0, v1);
                    *(__half2*)(Chi + rowoff + n) = hh;
                }
            }
        }
    }
}

// ---------------------------------------------------------------------------
// Tensor-core flash attention (R11/R12 design, unchanged)
// ---------------------------------------------------------------------------
#define AROWB 144
#define AQB   (128 * AROWB)
#define AKVB  (64 * AROWB)
#define ASM_MASK AQB
#define ASM_KV   (AQB + 2048)
#define ASTAGEB  (2 * AKVB)
#define ATT_SMEM (ASM_KV + 3 * ASTAGEB)

__global__ void __launch_bounds__(256) attn_kernel(
    const __half* __restrict__ QKVh,
    const int* __restrict__ mask,
    __half* __restrict__ Ch)
{
    extern __shared__ char sm[];
    const uint32_t sb = smem_u32(sm);

    const int qt = blockIdx.x;
    const int bh = blockIdx.y;
    const int b  = bh / NHH;
    const int h  = bh % NHH;
    const int t  = threadIdx.x;
    const int w  = t >> 5, lane = t & 31;

    const int ST = 3 * HH;
    const size_t rowbase = (size_t)b * SS;
    const int qcol = h * DHH, kcol = HH + h * DHH, vcol = 2 * HH + h * DHH;

    auto issueKV = [&](int kt, int s) {
        const uint32_t st = sb + ASM_KV + s * ASTAGEB;
#pragma unroll
        for (int j = 0; j < 4; j++) {
            const int idx = t + j * 256;
            const int mat = idx >> 9;
            const int rem = idx & 511;
            const int r = rem >> 3, c = rem & 7;
            const int col = mat ? vcol : kcol;
            const size_t g = (rowbase + kt * 64 + r) * ST + col + c * 8;
            CP16(st + mat * AKVB + r * AROWB + c * 16, QKVh + g);
        }
    };

#pragma unroll
    for (int j = 0; j < 4; j++) {
        const int idx = t + j * 256;
        const int r = idx >> 3, c = idx & 7;
        const size_t g = (rowbase + qt * 128 + r) * ST + qcol + c * 8;
        CP16(sb + r * AROWB + c * 16, QKVh + g);
    }
    {
        float* am = (float*)(sm + ASM_MASK);
#pragma unroll
        for (int j = 0; j < 2; j++) {
            const int i = t + j * 256;
            am[i] = (1.0f - (float)mask[b * SS + i]) * -10000.0f;
        }
    }
    issueKV(0, 0); CP_COMMIT();
    issueKV(1, 1); CP_COMMIT();

    float l0 = 0.f, l1 = 0.f;
    float oacc[8][4];
#pragma unroll
    for (int i = 0; i < 8; i++)
#pragma unroll
        for (int j = 0; j < 4; j++) oacc[i][j] = 0.f;

    const uint32_t a_off = (uint32_t)((w * 16 + (lane & 15)) * AROWB + ((lane >> 4) << 4));
    const uint32_t b_row = (uint32_t)(((lane & 7) | ((lane & 16) >> 1)) * AROWB
                                      + (((lane >> 3) & 1) << 4));
    const uint32_t v_row = (uint32_t)((lane & 15) * AROWB + ((lane >> 4) << 4));
    const float* am = (const float*)(sm + ASM_MASK);

    for (int kt = 0; kt < SS / 64; kt++) {
        if (kt + 1 < SS / 64) { CP_WAIT(1); } else { CP_WAIT(0); }
        __syncthreads();
        if (kt + 2 < SS / 64) { issueKV(kt + 2, (kt + 2) % 3); CP_COMMIT(); }

        const uint32_t sK = sb + ASM_KV + (kt % 3) * ASTAGEB;
        const uint32_t sV = sK + AKVB;

        float sacc[8][4];
#pragma unroll
        for (int i = 0; i < 8; i++)
#pragma unroll
            for (int j = 0; j < 4; j++) sacc[i][j] = 0.f;

#pragma unroll
        for (int ks = 0; ks < 4; ks++) {
            const uint32_t ko = ks * 32;
            uint32_t qh[4];
            LDM4(qh, sb + a_off + ko);
#pragma unroll
            for (int n2 = 0; n2 < 4; n2++) {
                uint32_t kh[4];
                LDM4(kh, sK + b_row + n2 * (16 * AROWB) + ko);
                MMAF16(sacc[n2 * 2],     qh, kh[0], kh[1]);
                MMAF16(sacc[n2 * 2 + 1], qh, kh[2], kh[3]);
            }
        }

        const int colbase = kt * 64 + (lane & 3) * 2;
        float ps0 = 0.f, ps1 = 0.f;
#pragma unroll
        for (int nt = 0; nt < 8; nt++) {
            const float a0 = am[colbase + nt * 8];
            const float a1 = am[colbase + nt * 8 + 1];
            sacc[nt][0] = __expf(fmaf(sacc[nt][0], 0.125f, a0));
            sacc[nt][1] = __expf(fmaf(sacc[nt][1], 0.125f, a1));
            sacc[nt][2] = __expf(fmaf(sacc[nt][2], 0.125f, a0));
            sacc[nt][3] = __expf(fmaf(sacc[nt][3], 0.125f, a1));
            ps0 += sacc[nt][0] + sacc[nt][1];
            ps1 += sacc[nt][2] + sacc[nt][3];
        }
        l0 += ps0; l1 += ps1;

#pragma unroll
        for (int ks = 0; ks < 4; ks++) {
            uint32_t ah[4];
#pragma unroll
            for (int pos = 0; pos < 4; pos++) {
                const int nt = 2 * ks + (pos >> 1);
                const int jb = (pos & 1) * 2;
                __half2 hh = __floats2half2_rn(sacc[nt][jb], sacc[nt][jb + 1]);
                ah[pos] = *(uint32_t*)&hh;
            }
#pragma unroll
            for (int dp = 0; dp < 4; dp++) {
                uint32_t vh[4];
                LDM4T(vh, sV + ks * (16 * AROWB) + v_row + dp * 32);
                MMAF16(oacc[dp * 2],     ah, vh[0], vh[1]);
                MMAF16(oacc[dp * 2 + 1], ah, vh[2], vh[3]);
            }
        }
    }

    l0 += __shfl_xor_sync(0xffffffffu, l0, 1);
    l0 += __shfl_xor_sync(0xffffffffu, l0, 2);
    l1 += __shfl_xor_sync(0xffffffffu, l1, 1);
    l1 += __shfl_xor_sync(0xffffffffu, l1, 2);
    const float inv0 = 1.0f / l0, inv1 = 1.0f / l1;

    const size_t row0 = (size_t)(b * SS + qt * 128 + w * 16 + (lane >> 2));
    const size_t row1 = row0 + 8;
    const int ocol = h * DHH + (lane & 3) * 2;
#pragma unroll
    for (int nt = 0; nt < 8; nt++) {
        const int n = ocol + nt * 8;
        __half2 h0 = __floats2half2_rn(oacc[nt][0] * inv0, oacc[nt][1] * inv0);
        __half2 h1 = __floats2half2_rn(oacc[nt][2] * inv1, oacc[nt][3] * inv1);
        *(__half2*)(Ch + row0 * HH + n) = h0;
        *(__half2*)(Ch + row1 * HH + n) = h1;
    }
}

// ---------------------------------------------------------------------------
// Row-wise LayerNorm; optional fp16 side output
// ---------------------------------------------------------------------------
template <int SPLIT>
__global__ void __launch_bounds__(256) ln_kernel(
    const float* __restrict__ X, const float* __restrict__ gg,
    const float* __restrict__ bb, float* __restrict__ Y,
    __half* __restrict__ Yh)
{
    const int row = blockIdx.x;
    const float* x = X + (size_t)row * HH;
    const int c = threadIdx.x;

    const float v0 = x[c];
    const float v1 = x[c + 256];
    const float v2 = x[c + 512];
    float s  = v0 + v1 + v2;
    float s2 = v0 * v0 + v1 * v1 + v2 * v2;

    __shared__ float sa[8], sb2[8];
    __shared__ float stats[2];
    const int lane = threadIdx.x & 31, w = threadIdx.x >> 5;
#pragma unroll
    for (int o = 16; o > 0; o >>= 1) {
        s  += __shfl_down_sync(0xffffffffu, s, o);
        s2 += __shfl_down_sync(0xffffffffu, s2, o);
    }
    if (lane == 0) { sa[w] = s; sb2[w] = s2; }
    __syncthreads();
    if (threadIdx.x == 0) {
        float ts = 0.f, ts2 = 0.f;
#pragma unroll
        for (int i = 0; i < 8; i++) { ts += sa[i]; ts2 += sb2[i]; }
        const float mu  = ts * (1.0f / HH);
        const float var = ts2 * (1.0f / HH) - mu * mu;
        stats[0] = mu;
        stats[1] = rsqrtf(var + LN_EPS);
    }
    __syncthreads();
    const float mu = stats[0], rstd = stats[1];
    const size_t ro = (size_t)row * HH;
#pragma unroll
    for (int j = 0; j < 3; j++) {
        const int cc = c + j * 256;
        const float vv = (j == 0 ? v0 : (j == 1 ? v1 : v2));
        const float y = (vv - mu) * rstd * gg[cc] + bb[cc];
        Y[ro + cc] = y;
        if (SPLIT) Yh[ro + cc] = __float2half_rn(y);
    }
}

// ---------------------------------------------------------------------------
// Launch
// ---------------------------------------------------------------------------
extern "C" void kernel_launch(void* const* d_in, const int* in_sizes, int n_in,
                              void* d_out, int out_size)
{
    (void)in_sizes; (void)n_in; (void)out_size;
    const float* x    = (const float*)d_in[0];
    const int*   mask = (const int*)  d_in[1];
    const float* Wq   = (const float*)d_in[2];
    const float* bq   = (const float*)d_in[3];
    const float* Wk   = (const float*)d_in[4];
    const float* bk   = (const float*)d_in[5];
    const float* Wv   = (const float*)d_in[6];
    const float* bv   = (const float*)d_in[7];
    const float* Wo   = (const float*)d_in[8];
    const float* bo   = (const float*)d_in[9];
    const float* ln1g = (const float*)d_in[10];
    const float* ln1b = (const float*)d_in[11];
    const float* W1   = (const float*)d_in[12];
    const float* b1   = (const float*)d_in[13];
    const float* W2   = (const float*)d_in[14];
    const float* b2   = (const float*)d_in[15];
    const float* ln2g = (const float*)d_in[16];
    const float* ln2b = (const float*)d_in[17];
    float* out = (float*)d_out;

    __half *xh, *qkvh, *ctxh, *h1h, *ffh;
    __half *wqkv, *wo, *w1, *w2;
    float *t1, *h1, *t2, *bqkv;
    cudaGetSymbolAddress((void**)&xh, g_xh);
    cudaGetSymbolAddress((void**)&qkvh, g_qkvh);
    cudaGetSymbolAddress((void**)&ctxh, g_ctxh);
    cudaGetSymbolAddress((void**)&h1h, g_h1h);
    cudaGetSymbolAddress((void**)&ffh, g_ffh);
    cudaGetSymbolAddress((void**)&wqkv, g_wqkv);
    cudaGetSymbolAddress((void**)&wo, g_wo);
    cudaGetSymbolAddress((void**)&w1, g_w1);
    cudaGetSymbolAddress((void**)&w2, g_w2);
    cudaGetSymbolAddress((void**)&t1, g_t1);
    cudaGetSymbolAddress((void**)&h1, g_h1);
    cudaGetSymbolAddress((void**)&t2, g_t2);
    cudaGetSymbolAddress((void**)&bqkv, g_bqkv);

    constexpr int SM128 = (128 + 64) * ROWB * NSTAGE;   // 55296 -> 4 CTA/SM
    constexpr int SM64  = (64 + 64) * ROWB * NSTAGE;    // 36864 -> 6 CTA/SM

    cudaFuncSetAttribute(attn_kernel,
                         cudaFuncAttributeMaxDynamicSharedMemorySize, ATT_SMEM);
    cudaFuncSetAttribute(tc_gemm<0, 2>,
                         cudaFuncAttributeMaxDynamicSharedMemorySize, SM128);
    cudaFuncSetAttribute(tc_gemm<1, 2>,
                         cudaFuncAttributeMaxDynamicSharedMemorySize, SM128);
    cudaFuncSetAttribute(tc_gemm<2, 1>,
                         cudaFuncAttributeMaxDynamicSharedMemorySize, SM64);

    prep_kernel<<<PREP_BLOCKS, 256>>>(Wq, Wk, Wv, Wo, W1, W2, x, bq, bk, bv,
                                      wqkv, wo, w1, w2, xh, bqkv);

    // fused QKV -> fp16  (36 x 32 = 1152 CTAs)
    tc_gemm<0, 2><<<dim3(3 * HH / 64, MM / 128), 256, SM128>>>(
        xh, wqkv, bqkv, nullptr, nullptr, qkvh, HH, 3 * HH);

    // attention -> ctx fp16
    attn_kernel<<<dim3(SS / 128, BB * NHH), 256, ATT_SMEM>>>(
        qkvh, mask, ctxh);

    // t1 = ctx @ Wo + bo + x  (12 x 64 = 768 CTAs)
    tc_gemm<2, 1><<<dim3(HH / 64, MM / 64), 256, SM64>>>(
        ctxh, wo, bo, x, t1, nullptr, HH, HH);
    ln_kernel<1><<<MM, 256>>>(t1, ln1g, ln1b, h1, h1h);

    // ff = gelu(h1 @ W1 + b1)  (48 x 32 = 1536 CTAs)
    tc_gemm<1, 2><<<dim3(FFF / 64, MM / 128), 256, SM128>>>(
        h1h, w1, b1, nullptr, nullptr, ffh, HH, FFF);

    // t2 = ff @ W2 + b2 + h1  (12 x 64 = 768 CTAs)
    tc_gemm<2, 1><<<dim3(HH / 64, MM / 64), 256, SM64>>>(
        ffh, w2, b2, h1, t2, nullptr, FFF, HH);
    ln_kernel<0><<<MM, 256>>>(t2, ln2g, ln2b, out, nullptr);
}

// round 14
// speedup vs baseline: 1.1103x; 1.1103x over previous
#include <cuda_runtime.h>
#include <cuda_fp16.h>
#include <math.h>
#include <stdint.h>

#define BB   8
#define SS   512
#define HH   768
#define NHH  12
#define DHH  64
#define FFF  3072
#define MM   (BB * SS)
#define LN_EPS 1e-3f

// ---------------------------------------------------------------------------
// Scratch
// ---------------------------------------------------------------------------
__device__ __align__(16) __half g_xh  [MM * HH];
__device__ __align__(16) __half g_qkvh[MM * 3 * HH];
__device__ __align__(16) __half g_ctxh[MM * HH];
__device__ __align__(16) float g_t1 [MM * HH];
__device__ __align__(16) float g_h1 [MM * HH];
__device__ __align__(16) __half g_h1h[MM * HH];
__device__ __align__(16) __half g_ffh[MM * FFF];
__device__ __align__(16) float g_t2 [MM * HH];
__device__ __align__(16) __half g_wqkv[3 * HH * HH];
__device__ __align__(16) float g_bqkv[3 * HH];
__device__ __align__(16) __half g_wo [HH * HH];
__device__ __align__(16) __half g_w1 [FFF * HH];
__device__ __align__(16) __half g_w2 [HH * FFF];

// ---------------------------------------------------------------------------
// PTX wrappers
// ---------------------------------------------------------------------------
__device__ __forceinline__ uint32_t smem_u32(const void* p) {
    uint32_t a;
    asm("{ .reg .u64 t; cvta.to.shared.u64 t, %1; cvt.u32.u64 %0, t; }"
        : "=r"(a) : "l"(p));
    return a;
}
#define LDM4(R, ADDR) \
    asm volatile("ldmatrix.sync.aligned.m8n8.x4.shared.b16 {%0,%1,%2,%3}, [%4];" \
        : "=r"((R)[0]), "=r"((R)[1]), "=r"((R)[2]), "=r"((R)[3]) : "r"(ADDR))
#define LDM4T(R, ADDR) \
    asm volatile("ldmatrix.sync.aligned.m8n8.x4.trans.shared.b16 {%0,%1,%2,%3}, [%4];" \
        : "=r"((R)[0]), "=r"((R)[1]), "=r"((R)[2]), "=r"((R)[3]) : "r"(ADDR))
#define MMAF16(D, A, B0, B1) \
    asm volatile("mma.sync.aligned.m16n8k16.row.col.f32.f16.f16.f32 " \
        "{%0,%1,%2,%3}, {%4,%5,%6,%7}, {%8,%9}, {%0,%1,%2,%3};" \
        : "+f"((D)[0]), "+f"((D)[1]), "+f"((D)[2]), "+f"((D)[3]) \
        : "r"((A)[0]), "r"((A)[1]), "r"((A)[2]), "r"((A)[3]), "r"(B0), "r"(B1))
#define CP16(SADDR, GPTR) \
    asm volatile("cp.async.cg.shared.global [%0], [%1], 16;" \
        :: "r"(SADDR), "l"(GPTR))
#define CP_COMMIT() asm volatile("cp.async.commit_group;" ::: "memory")
#define CP_WAIT(N)  asm volatile("cp.async.wait_group %0;" :: "n"(N) : "memory")
#define EX2F16X2(R, A) \
    asm volatile("ex2.approx.f16x2 %0, %1;" : "=r"(R) : "r"(A))

__device__ __forceinline__ float gelu_f(float x) {
    return 0.5f * x * (1.0f + erff(x * 0.70710678118654752f));
}

// ---------------------------------------------------------------------------
// Fused prep kernel (mask row now stores maskval * log2e premultiplied later
// in attention; here unchanged weight/x prep)
// ---------------------------------------------------------------------------
#define PREP_BLOCKS 9985

__global__ void __launch_bounds__(256) prep_kernel(
    const float* __restrict__ Wq, const float* __restrict__ Wk,
    const float* __restrict__ Wv, const float* __restrict__ Wo,
    const float* __restrict__ W1, const float* __restrict__ W2,
    const float* __restrict__ x,
    const float* __restrict__ bq, const float* __restrict__ bk,
    const float* __restrict__ bv,
    __half* __restrict__ wqkv, __half* __restrict__ wo,
    __half* __restrict__ w1, __half* __restrict__ w2,
    __half* __restrict__ xh, float* __restrict__ bqkv)
{
    __shared__ float tile[32][33];
    const int id = blockIdx.x;
    const int t  = threadIdx.x;
    const int tx = t & 31, ty = t >> 5;

    const float* in = nullptr;
    __half* out = nullptr;
    int K = 0, N = 0, bx = 0, by = 0;

    if (id < 2304) {
        const int z = id / 576, within = id % 576;
        in  = (z == 0) ? Wq : (z == 1) ? Wk : (z == 2) ? Wv : Wo;
        out = (z < 3) ? (wqkv + z * HH * HH) : wo;
        K = HH; N = HH; bx = within % 24; by = within / 24;
    } else if (id < 4608) {
        const int within = id - 2304;
        in = W1; out = w1; K = HH; N = FFF;
        bx = within % 96; by = within / 96;
    } else if (id < 6912) {
        const int within = id - 4608;
        in = W2; out = w2; K = FFF; N = HH;
        bx = within % 24; by = within / 24;
    } else if (id < 9984) {
        const int i = (id - 6912) * 256 + t;
        const float4 v = *(const float4*)(x + (size_t)i * 4);
        __half2 h0 = __floats2half2_rn(v.x, v.y);
        __half2 h1 = __floats2half2_rn(v.z, v.w);
        uint2 u; u.x = *(uint32_t*)&h0; u.y = *(uint32_t*)&h1;
        *(uint2*)(xh + (size_t)i * 4) = u;
        return;
    } else {
        for (int i = t; i < HH; i += 256) {
            bqkv[i] = bq[i]; bqkv[HH + i] = bk[i]; bqkv[2 * HH + i] = bv[i];
        }
        return;
    }

    const int n0 = bx * 32, k0 = by * 32;
#pragma unroll
    for (int j = 0; j < 32; j += 8)
        tile[ty + j][tx] = in[(size_t)(k0 + ty + j) * N + n0 + tx];
    __syncthreads();
#pragma unroll
    for (int j = 0; j < 32; j += 8)
        out[(size_t)(n0 + ty + j) * K + k0 + tx] = __float2half_rn(tile[tx][ty + j]);
}

// ---------------------------------------------------------------------------
// GEMM (R12 config, best known): fp16, KC=64, 2-stage, 1 sync/chunk.
// BN=128, warp grid 2x4, warp tile (16*MT)x32. MT=4 -> BM=128; MT=2 -> BM=64.
// ---------------------------------------------------------------------------
#define KC 64
#define ROWB 144
#define NSTAGE 2

template <int EPI, int MT>
__global__ void __launch_bounds__(256) tc_gemm(
    const __half* __restrict__ Ahi,
    const __half* __restrict__ Whi,
    const float* __restrict__ bias, const float* __restrict__ resid,
    float* __restrict__ C, __half* __restrict__ Chi,
    int K, int Ntot)
{
    constexpr int BM = MT * 32;
    constexpr int AMATB = BM * ROWB;
    constexpr int BMATB = 128 * ROWB;
    constexpr int STAGEB = AMATB + BMATB;
    constexpr int ACH = BM * 8;
    constexpr int NCHK = (ACH + 1024) / 256;

    extern __shared__ char sm[];
    const uint32_t sb = smem_u32(sm);

    const int t    = threadIdx.x;
    const int wid  = t >> 5, lane = t & 31;
    const int wm   = wid >> 2;
    const int wn   = wid & 3;
    const int bn   = blockIdx.x, bm = blockIdx.y;
    const int rbase = bm * BM, cbase = bn * 128;
    const int nch  = K / KC;

    auto issue = [&](int ci) {
        const int s = ci & 1;
        const uint32_t st = sb + s * STAGEB;
        const int kt = ci * KC;
#pragma unroll
        for (int j = 0; j < NCHK; j++) {
            int id = t + j * 256;
            if (id < ACH) {
                const int r = id >> 3, c = id & 7;
                CP16(st + r * ROWB + c * 16,
                     Ahi + (size_t)(rbase + r) * K + kt + c * 8);
            } else {
                id -= ACH;
                const int r = id >> 3, c = id & 7;
                CP16(st + AMATB + r * ROWB + c * 16,
                     Whi + (size_t)(cbase + r) * K + kt + c * 8);
            }
        }
    };

    float acc[MT][4][4];
#pragma unroll
    for (int i = 0; i < MT; i++)
#pragma unroll
        for (int j = 0; j < 4; j++)
#pragma unroll
            for (int q = 0; q < 4; q++) acc[i][j][q] = 0.f;

    const uint32_t a_off = (uint32_t)((wm * (MT * 16) + (lane & 15)) * ROWB
                                      + ((lane >> 4) << 4));
    const uint32_t b_off = (uint32_t)((wn * 32 + ((lane & 7) | ((lane & 16) >> 1))) * ROWB
                                      + (((lane >> 3) & 1) << 4));

    issue(0); CP_COMMIT();

    for (int ci = 0; ci < nch; ci++) {
        CP_WAIT(0);
        __syncthreads();
        if (ci + 1 < nch) { issue(ci + 1); CP_COMMIT(); }

        const uint32_t sA  = sb + (ci & 1) * STAGEB;
        const uint32_t sBh = sA + AMATB;
#pragma unroll
        for (int ks = 0; ks < 4; ks++) {
            const uint32_t ko = ks * 32;
            uint32_t AH[MT][4], BH[2][4];
#pragma unroll
            for (int mt = 0; mt < MT; mt++)
                LDM4(AH[mt], sA + a_off + mt * (16 * ROWB) + ko);
#pragma unroll
            for (int n2 = 0; n2 < 2; n2++)
                LDM4(BH[n2], sBh + b_off + n2 * (16 * ROWB) + ko);
#pragma unroll
            for (int mt = 0; mt < MT; mt++) {
#pragma unroll
                for (int nt = 0; nt < 4; nt++) {
                    const uint32_t b0 = BH[nt >> 1][(nt & 1) * 2];
                    const uint32_t b1 = BH[nt >> 1][(nt & 1) * 2 + 1];
                    MMAF16(acc[mt][nt], AH[mt], b0, b1);
                }
            }
        }
    }

    const int mrow0 = rbase + wm * (MT * 16) + (lane >> 2);
    const int ncol0 = cbase + wn * 32 + (lane & 3) * 2;
#pragma unroll
    for (int mt = 0; mt < MT; mt++) {
#pragma unroll
        for (int half = 0; half < 2; half++) {
            const int m = mrow0 + mt * 16 + half * 8;
            const size_t rowoff = (size_t)m * Ntot;
#pragma unroll
            for (int nt = 0; nt < 4; nt++) {
                const int n = ncol0 + nt * 8;
                float v0 = acc[mt][nt][half * 2 + 0];
                float v1 = acc[mt][nt][half * 2 + 1];
                const float2 bv = *(const float2*)(bias + n);
                v0 += bv.x; v1 += bv.y;
                if (EPI == 2) {
                    const float2 rv = *(const float2*)(resid + rowoff + n);
                    v0 += rv.x; v1 += rv.y;
                    *(float2*)(C + rowoff + n) = make_float2(v0, v1);
                } else {
                    if (EPI == 1) { v0 = gelu_f(v0); v1 = gelu_f(v1); }
                    __half2 hh = __floats2half2_rn(v0, v1);
                    *(__half2*)(Chi + rowoff + n) = hh;
                }
            }
        }
    }
}

// ---------------------------------------------------------------------------
// Tensor-core flash attention: fp16, shift-free base-2 softmax via
// ex2.approx.f16x2 (2 probs / MUFU op, result IS the PV A-fragment),
// row sums l computed by an extra ones-column MMA (no scalar sums, no shfl).
// 256 threads, Q tile 128 rows, 3-stage KV, 1 sync/tile.
// ---------------------------------------------------------------------------
#define AROWB 144
#define AQB   (128 * AROWB)
#define AKVB  (64 * AROWB)
#define ASM_MASK AQB
#define ASM_KV   (AQB + 2048)
#define ASTAGEB  (2 * AKVB)
#define ATT_SMEM (ASM_KV + 3 * ASTAGEB)
#define ONES2 0x3C003C00u
#define SCL_L2E 0.180336880f     // 0.125 * log2(e)
#define L2E     1.44269504f

__global__ void __launch_bounds__(256) attn_kernel(
    const __half* __restrict__ QKVh,
    const int* __restrict__ mask,
    __half* __restrict__ Ch)
{
    extern __shared__ char sm[];
    const uint32_t sb = smem_u32(sm);

    const int qt = blockIdx.x;
    const int bh = blockIdx.y;
    const int b  = bh / NHH;
    const int h  = bh % NHH;
    const int t  = threadIdx.x;
    const int w  = t >> 5, lane = t & 31;

    const int ST = 3 * HH;
    const size_t rowbase = (size_t)b * SS;
    const int qcol = h * DHH, kcol = HH + h * DHH, vcol = 2 * HH + h * DHH;

    auto issueKV = [&](int kt, int s) {
        const uint32_t st = sb + ASM_KV + s * ASTAGEB;
#pragma unroll
        for (int j = 0; j < 4; j++) {
            const int idx = t + j * 256;
            const int mat = idx >> 9;
            const int rem = idx & 511;
            const int r = rem >> 3, c = rem & 7;
            const int col = mat ? vcol : kcol;
            const size_t g = (rowbase + kt * 64 + r) * ST + col + c * 8;
            CP16(st + mat * AKVB + r * AROWB + c * 16, QKVh + g);
        }
    };

#pragma unroll
    for (int j = 0; j < 4; j++) {
        const int idx = t + j * 256;
        const int r = idx >> 3, c = idx & 7;
        const size_t g = (rowbase + qt * 128 + r) * ST + qcol + c * 8;
        CP16(sb + r * AROWB + c * 16, QKVh + g);
    }
    {
        float* am = (float*)(sm + ASM_MASK);
#pragma unroll
        for (int j = 0; j < 2; j++) {
            const int i = t + j * 256;
            // premultiplied by log2(e) for base-2 exp
            am[i] = (1.0f - (float)mask[b * SS + i]) * (-10000.0f * L2E);
        }
    }
    issueKV(0, 0); CP_COMMIT();
    issueKV(1, 1); CP_COMMIT();

    float lacc[4] = {0.f, 0.f, 0.f, 0.f};   // ones-MMA row sums
    float oacc[8][4];
#pragma unroll
    for (int i = 0; i < 8; i++)
#pragma unroll
        for (int j = 0; j < 4; j++) oacc[i][j] = 0.f;

    const uint32_t a_off = (uint32_t)((w * 16 + (lane & 15)) * AROWB + ((lane >> 4) << 4));
    const uint32_t b_row = (uint32_t)(((lane & 7) | ((lane & 16) >> 1)) * AROWB
                                      + (((lane >> 3) & 1) << 4));
    const uint32_t v_row = (uint32_t)((lane & 15) * AROWB + ((lane >> 4) << 4));
    const float* am = (const float*)(sm + ASM_MASK);

    for (int kt = 0; kt < SS / 64; kt++) {
        if (kt + 1 < SS / 64) { CP_WAIT(1); } else { CP_WAIT(0); }
        __syncthreads();
        if (kt + 2 < SS / 64) { issueKV(kt + 2, (kt + 2) % 3); CP_COMMIT(); }

        const uint32_t sK = sb + ASM_KV + (kt % 3) * ASTAGEB;
        const uint32_t sV = sK + AKVB;

        float sacc[8][4];
#pragma unroll
        for (int i = 0; i < 8; i++)
#pragma unroll
            for (int j = 0; j < 4; j++) sacc[i][j] = 0.f;

#pragma unroll
        for (int ks = 0; ks < 4; ks++) {
            const uint32_t ko = ks * 32;
            uint32_t qh[4];
            LDM4(qh, sb + a_off + ko);
#pragma unroll
            for (int n2 = 0; n2 < 4; n2++) {
                uint32_t kh[4];
                LDM4(kh, sK + b_row + n2 * (16 * AROWB) + ko);
                MMAF16(sacc[n2 * 2],     qh, kh[0], kh[1]);
                MMAF16(sacc[n2 * 2 + 1], qh, kh[2], kh[3]);
            }
        }

        // p = 2^(s*0.125*log2e + mask*log2e), two probs per MUFU op.
        // pa[nt] = probs rows r, pb[nt] = probs rows r+8 (A-fragment pairs).
        const int colbase = kt * 64 + (lane & 3) * 2;
        uint32_t pa[8], pb[8];
#pragma unroll
        for (int nt = 0; nt < 8; nt++) {
            const float a0 = am[colbase + nt * 8];
            const float a1 = am[colbase + nt * 8 + 1];
            const float t0 = fmaf(sacc[nt][0], SCL_L2E, a0);
            const float t1 = fmaf(sacc[nt][1], SCL_L2E, a1);
            const float t2 = fmaf(sacc[nt][2], SCL_L2E, a0);
            const float t3 = fmaf(sacc[nt][3], SCL_L2E, a1);
            __half2 hA = __floats2half2_rn(t0, t1);
            __half2 hB = __floats2half2_rn(t2, t3);
            EX2F16X2(pa[nt], *(uint32_t*)&hA);
            EX2F16X2(pb[nt], *(uint32_t*)&hB);
        }

#pragma unroll
        for (int ks = 0; ks < 4; ks++) {
            uint32_t ah[4];
            ah[0] = pa[2 * ks];
            ah[1] = pb[2 * ks];
            ah[2] = pa[2 * ks + 1];
            ah[3] = pb[2 * ks + 1];
            // row-sum accumulation: P @ ones
            MMAF16(lacc, ah, ONES2, ONES2);
#pragma unroll
            for (int dp = 0; dp < 4; dp++) {
                uint32_t vh[4];
                LDM4T(vh, sV + ks * (16 * AROWB) + v_row + dp * 32);
                MMAF16(oacc[dp * 2],     ah, vh[0], vh[1]);
                MMAF16(oacc[dp * 2 + 1], ah, vh[2], vh[3]);
            }
        }
    }

    const float inv0 = 1.0f / lacc[0], inv1 = 1.0f / lacc[2];

    const size_t row0 = (size_t)(b * SS + qt * 128 + w * 16 + (lane >> 2));
    const size_t row1 = row0 + 8;
    const int ocol = h * DHH + (lane & 3) * 2;
#pragma unroll
    for (int nt = 0; nt < 8; nt++) {
        const int n = ocol + nt * 8;
        __half2 h0 = __floats2half2_rn(oacc[nt][0] * inv0, oacc[nt][1] * inv0);
        __half2 h1 = __floats2half2_rn(oacc[nt][2] * inv1, oacc[nt][3] * inv1);
        *(__half2*)(Ch + row0 * HH + n) = h0;
        *(__half2*)(Ch + row1 * HH + n) = h1;
    }
}

// ---------------------------------------------------------------------------
// Row-wise LayerNorm; optional fp16 side output
// ---------------------------------------------------------------------------
template <int SPLIT>
__global__ void __launch_bounds__(256) ln_kernel(
    const float* __restrict__ X, const float* __restrict__ gg,
    const float* __restrict__ bb, float* __restrict__ Y,
    __half* __restrict__ Yh)
{
    const int row = blockIdx.x;
    const float* x = X + (size_t)row * HH;
    const int c = threadIdx.x;

    const float v0 = x[c];
    const float v1 = x[c + 256];
    const float v2 = x[c + 512];
    float s  = v0 + v1 + v2;
    float s2 = v0 * v0 + v1 * v1 + v2 * v2;

    __shared__ float sa[8], sb2[8];
    __shared__ float stats[2];
    const int lane = threadIdx.x & 31, w = threadIdx.x >> 5;
#pragma unroll
    for (int o = 16; o > 0; o >>= 1) {
        s  += __shfl_down_sync(0xffffffffu, s, o);
        s2 += __shfl_down_sync(0xffffffffu, s2, o);
    }
    if (lane == 0) { sa[w] = s; sb2[w] = s2; }
    __syncthreads();
    if (threadIdx.x == 0) {
        float ts = 0.f, ts2 = 0.f;
#pragma unroll
        for (int i = 0; i < 8; i++) { ts += sa[i]; ts2 += sb2[i]; }
        const float mu  = ts * (1.0f / HH);
        const float var = ts2 * (1.0f / HH) - mu * mu;
        stats[0] = mu;
        stats[1] = rsqrtf(var + LN_EPS);
    }
    __syncthreads();
    const float mu = stats[0], rstd = stats[1];
    const size_t ro = (size_t)row * HH;
#pragma unroll
    for (int j = 0; j < 3; j++) {
        const int cc = c + j * 256;
        const float vv = (j == 0 ? v0 : (j == 1 ? v1 : v2));
        const float y = (vv - mu) * rstd * gg[cc] + bb[cc];
        Y[ro + cc] = y;
        if (SPLIT) Yh[ro + cc] = __float2half_rn(y);
    }
}

// ---------------------------------------------------------------------------
// Launch
// ---------------------------------------------------------------------------
extern "C" void kernel_launch(void* const* d_in, const int* in_sizes, int n_in,
                              void* d_out, int out_size)
{
    (void)in_sizes; (void)n_in; (void)out_size;
    const float* x    = (const float*)d_in[0];
    const int*   mask = (const int*)  d_in[1];
    const float* Wq   = (const float*)d_in[2];
    const float* bq   = (const float*)d_in[3];
    const float* Wk   = (const float*)d_in[4];
    const float* bk   = (const float*)d_in[5];
    const float* Wv   = (const float*)d_in[6];
    const float* bv   = (const float*)d_in[7];
    const float* Wo   = (const float*)d_in[8];
    const float* bo   = (const float*)d_in[9];
    const float* ln1g = (const float*)d_in[10];
    const float* ln1b = (const float*)d_in[11];
    const float* W1   = (const float*)d_in[12];
    const float* b1   = (const float*)d_in[13];
    const float* W2   = (const float*)d_in[14];
    const float* b2   = (const float*)d_in[15];
    const float* ln2g = (const float*)d_in[16];
    const float* ln2b = (const float*)d_in[17];
    float* out = (float*)d_out;

    __half *xh, *qkvh, *ctxh, *h1h, *ffh;
    __half *wqkv, *wo, *w1, *w2;
    float *t1, *h1, *t2, *bqkv;
    cudaGetSymbolAddress((void**)&xh, g_xh);
    cudaGetSymbolAddress((void**)&qkvh, g_qkvh);
    cudaGetSymbolAddress((void**)&ctxh, g_ctxh);
    cudaGetSymbolAddress((void**)&h1h, g_h1h);
    cudaGetSymbolAddress((void**)&ffh, g_ffh);
    cudaGetSymbolAddress((void**)&wqkv, g_wqkv);
    cudaGetSymbolAddress((void**)&wo, g_wo);
    cudaGetSymbolAddress((void**)&w1, g_w1);
    cudaGetSymbolAddress((void**)&w2, g_w2);
    cudaGetSymbolAddress((void**)&t1, g_t1);
    cudaGetSymbolAddress((void**)&h1, g_h1);
    cudaGetSymbolAddress((void**)&t2, g_t2);
    cudaGetSymbolAddress((void**)&bqkv, g_bqkv);

    constexpr int SM128 = (128 + 128) * ROWB * NSTAGE;   // 73728
    constexpr int SM64  = (64 + 128) * ROWB * NSTAGE;    // 55296

    cudaFuncSetAttribute(attn_kernel,
                         cudaFuncAttributeMaxDynamicSharedMemorySize, ATT_SMEM);
    cudaFuncSetAttribute(tc_gemm<0, 4>,
                         cudaFuncAttributeMaxDynamicSharedMemorySize, SM128);
    cudaFuncSetAttribute(tc_gemm<1, 4>,
                         cudaFuncAttributeMaxDynamicSharedMemorySize, SM128);
    cudaFuncSetAttribute(tc_gemm<2, 2>,
                         cudaFuncAttributeMaxDynamicSharedMemorySize, SM64);

    prep_kernel<<<PREP_BLOCKS, 256>>>(Wq, Wk, Wv, Wo, W1, W2, x, bq, bk, bv,
                                      wqkv, wo, w1, w2, xh, bqkv);

    tc_gemm<0, 4><<<dim3(3 * HH / 128, MM / 128), 256, SM128>>>(
        xh, wqkv, bqkv, nullptr, nullptr, qkvh, HH, 3 * HH);

    attn_kernel<<<dim3(SS / 128, BB * NHH), 256, ATT_SMEM>>>(
        qkvh, mask, ctxh);

    tc_gemm<2, 2><<<dim3(HH / 128, MM / 64), 256, SM64>>>(
        ctxh, wo, bo, x, t1, nullptr, HH, HH);
    ln_kernel<1><<<MM, 256>>>(t1, ln1g, ln1b, h1, h1h);

    tc_gemm<1, 4><<<dim3(FFF / 128, MM / 128), 256, SM128>>>(
        h1h, w1, b1, nullptr, nullptr, ffh, HH, FFF);

    tc_gemm<2, 2><<<dim3(HH / 128, MM / 64), 256, SM64>>>(
        ffh, w2, b2, h1, t2, nullptr, FFF, HH);
    ln_kernel<0><<<MM, 256>>>(t2, ln2g, ln2b, out, nullptr);
}